// round 3
// baseline (speedup 1.0000x reference)
#include <cuda_runtime.h>
#include <cuda_bf16.h>

#define DIM 4096
#define DIM4 (DIM / 4)   // 1024 float4s per row

// Gathered per-dim weight, precomputed per launch (graph-capturable,
// allocation-free: __device__ global scratch).
__device__ float g_w[DIM];

// shard_map may be int32 (JAX x64 disabled) or int64. Detect at runtime:
// shard_map[512] == 1 by construction (d // 512). As an int32 view:
//   int32 buffer: arr32[512] == 1
//   int64 buffer: arr32[512] == low word of element 256 == 0
__global__ void gather_w_kernel(const float* __restrict__ shards,
                                const int* __restrict__ map32,
                                int num_shards) {
    int d = blockIdx.x * blockDim.x + threadIdx.x;
    if (d < DIM) {
        bool is_int64 = (map32[512] == 0);
        int s = is_int64 ? map32[2 * d] : map32[d];
        // clamp for safety against any dtype misread
        s = min(max(s, 0), num_shards - 1);
        g_w[d] = shards[(long long)s * DIM + d];
    }
}

__global__ void __launch_bounds__(256) scale_kernel(const float4* __restrict__ x,
                                                    float4* __restrict__ out,
                                                    long long n4) {
    long long i = (long long)blockIdx.x * blockDim.x + threadIdx.x;
    if (i < n4) {
        int d4 = (int)(i & (DIM4 - 1));   // position within the DIM row
        const float4* w4p = reinterpret_cast<const float4*>(g_w);
        float4 xv = x[i];
        float4 wv = __ldg(&w4p[d4]);
        float4 o;
        o.x = xv.x * wv.x;
        o.y = xv.y * wv.y;
        o.z = xv.z * wv.z;
        o.w = xv.w * wv.w;
        out[i] = o;
    }
}

extern "C" void kernel_launch(void* const* d_in, const int* in_sizes, int n_in,
                              void* d_out, int out_size) {
    const float* x         = (const float*)d_in[0];
    const float* shards    = (const float*)d_in[1];
    const int*   map32     = (const int*)d_in[2];   // int32 view; kernel decodes
    float* out = (float*)d_out;

    int num_shards = in_sizes[1] / DIM;             // 32768 / 4096 = 8
    long long n  = (long long)in_sizes[0];          // total elements of x
    long long n4 = n / 4;

    gather_w_kernel<<<(DIM + 255) / 256, 256>>>(shards, map32, num_shards);

    long long blocks = (n4 + 255) / 256;
    scale_kernel<<<(unsigned)blocks, 256>>>(
        reinterpret_cast<const float4*>(x),
        reinterpret_cast<float4*>(out),
        n4);
}

// round 4
// speedup vs baseline: 1.0205x; 1.0205x over previous
#include <cuda_runtime.h>
#include <cuda_bf16.h>

#define DIM 4096
#define DIM4 (DIM / 4)   // 1024 float4s per row
#define UNROLL 4
#define TPB 256

// Gathered per-dim weight, precomputed per launch (graph-capturable,
// allocation-free: __device__ global scratch).
__device__ float g_w[DIM];

// shard_map may be int32 (JAX x64 disabled) or int64. Runtime detect:
// shard_map[512] == 1 by construction. As an int32 view:
//   int32 buffer: arr32[512] == 1
//   int64 buffer: arr32[512] == low word of element 256 == 0
__global__ void gather_w_kernel(const float* __restrict__ shards,
                                const int* __restrict__ map32,
                                int num_shards) {
    int d = blockIdx.x * blockDim.x + threadIdx.x;
    if (d < DIM) {
        bool is_int64 = (map32[512] == 0);
        int s = is_int64 ? map32[2 * d] : map32[d];
        s = min(max(s, 0), num_shards - 1);
        g_w[d] = shards[(long long)s * DIM + d];
    }
}

// One block per DIM row: 1024 float4s, 4 per thread, block-strided so every
// LDG/STG is a fully-coalesced 128B-per-quad access and the 4 loads per
// thread are independent (MLP_p1 = 4).
__global__ void __launch_bounds__(TPB) scale_kernel(const float4* __restrict__ x,
                                                    float4* __restrict__ out) {
    long long base = (long long)blockIdx.x * DIM4 + threadIdx.x;
    const float4* __restrict__ w4p = reinterpret_cast<const float4*>(g_w);

    float4 xv[UNROLL];
#pragma unroll
    for (int k = 0; k < UNROLL; k++)
        xv[k] = __ldcs(&x[base + k * TPB]);

    float4 wv[UNROLL];
#pragma unroll
    for (int k = 0; k < UNROLL; k++)
        wv[k] = w4p[threadIdx.x + k * TPB];

#pragma unroll
    for (int k = 0; k < UNROLL; k++) {
        float4 o;
        o.x = xv[k].x * wv[k].x;
        o.y = xv[k].y * wv[k].y;
        o.z = xv[k].z * wv[k].z;
        o.w = xv[k].w * wv[k].w;
        __stcs(&out[base + k * TPB], o);
    }
}

extern "C" void kernel_launch(void* const* d_in, const int* in_sizes, int n_in,
                              void* d_out, int out_size) {
    const float* x      = (const float*)d_in[0];
    const float* shards = (const float*)d_in[1];
    const int*   map32  = (const int*)d_in[2];   // int32 view; kernel decodes
    float* out = (float*)d_out;

    int num_shards = in_sizes[1] / DIM;          // 8
    long long n  = (long long)in_sizes[0];       // total elements of x
    long long nrows = n / DIM;                   // 16384 rows

    gather_w_kernel<<<(DIM + 255) / 256, 256>>>(shards, map32, num_shards);

    scale_kernel<<<(unsigned)nrows, TPB>>>(
        reinterpret_cast<const float4*>(x),
        reinterpret_cast<float4*>(out));
}

// round 5
// speedup vs baseline: 1.0383x; 1.0174x over previous
#include <cuda_runtime.h>
#include <cuda_bf16.h>

#define DIM 4096
#define DIM4 (DIM / 4)   // 1024 float4s per row
#define UNROLL 4
#define TPB 256

// Fully fused: each block owns one DIM row. Weights are gathered on the fly —
// shard blocks are 512 dims wide, so a float4 of dims never crosses a shard
// boundary; one map lookup + one gathered shards float4 per weight quad.
// Both the map (16 KB) and shards table (128 KB) are L2-resident, so these
// extra loads ride in the huge issue slack of this DRAM-bound stream.
//
// shard_map dtype is runtime-detected (int32 vs int64 viewed as int32 pairs):
// shard_map[512] == 1 by construction; as int32 view, an int64 buffer gives
// arr32[512] == 0 (low word of element 256).
__global__ void __launch_bounds__(TPB) fused_scale_kernel(
    const float4* __restrict__ x,
    const float4* __restrict__ shards4,   // [num_shards][DIM4]
    const int*    __restrict__ map32,
    float4* __restrict__ out,
    int num_shards)
{
    const bool is_int64 = (map32[512] == 0);
    const long long base = (long long)blockIdx.x * DIM4 + threadIdx.x;

    float4 xv[UNROLL];
#pragma unroll
    for (int k = 0; k < UNROLL; k++)
        xv[k] = __ldcs(&x[base + k * TPB]);

    float4 wv[UNROLL];
#pragma unroll
    for (int k = 0; k < UNROLL; k++) {
        int d4 = threadIdx.x + k * TPB;       // float4 index within row
        int d  = d4 * 4;                      // first dim of this quad
        int s  = is_int64 ? __ldg(&map32[2 * d]) : __ldg(&map32[d]);
        s = min(max(s, 0), num_shards - 1);
        wv[k] = __ldg(&shards4[(long long)s * DIM4 + d4]);
    }

#pragma unroll
    for (int k = 0; k < UNROLL; k++) {
        float4 o;
        o.x = xv[k].x * wv[k].x;
        o.y = xv[k].y * wv[k].y;
        o.z = xv[k].z * wv[k].z;
        o.w = xv[k].w * wv[k].w;
        __stcs(&out[base + k * TPB], o);
    }
}

extern "C" void kernel_launch(void* const* d_in, const int* in_sizes, int n_in,
                              void* d_out, int out_size) {
    const float* x      = (const float*)d_in[0];
    const float* shards = (const float*)d_in[1];
    const int*   map32  = (const int*)d_in[2];   // int32 view; kernel decodes
    float* out = (float*)d_out;

    int num_shards = in_sizes[1] / DIM;          // 8
    long long n     = (long long)in_sizes[0];    // total elements of x
    long long nrows = n / DIM;                   // 16384 rows

    fused_scale_kernel<<<(unsigned)nrows, TPB>>>(
        reinterpret_cast<const float4*>(x),
        reinterpret_cast<const float4*>(shards),
        map32,
        reinterpret_cast<float4*>(out),
        num_shards);
}